// round 5
// baseline (speedup 1.0000x reference)
#include <cuda_runtime.h>
#include <mma.h>
#include <cstdint>
#include <math.h>
using namespace nvcuda;

#define BATCH 64
#define C 128
#define HW 3136
#define KSPLIT 7
#define KPART 448        // HW / KSPLIT
#define NCHUNK 14        // KPART / 32
#define NUM_ITER 5
#define TRIU 8256
#define XLD 36           // SYRK chunk smem ld
#define MLD 132          // NS master ld
#define SLD 132          // NS slab ld (k-major)

__device__ float g_G[KSPLIT][BATCH][C][C];
__device__ float g_s[KSPLIT][BATCH][C];

// 36 upper-tri 16x16 frag tiles distributed over 8 warps (5,5,5,5,4,4,4,4)
__constant__ int8_t c_TI[36] = {0,0,0,0,0, 0,0,0,1,1, 1,1,1,1,1, 2,2,2,2,2,
                                2,3,3,3, 3,3,4,4, 4,4,5,5, 5,6,6,7};
__constant__ int8_t c_TJ[36] = {0,1,2,3,4, 5,6,7,1,2, 3,4,5,6,7, 2,3,4,5,6,
                                7,3,4,5, 6,7,4,5, 6,7,5,6, 7,6,7,7};
__constant__ int8_t c_WS[9]  = {0,5,10,15,20,24,28,32,36};

__device__ __forceinline__ float rtf32(float f) {
    uint32_t u; asm("cvt.rna.tf32.f32 %0, %1;" : "=r"(u) : "f"(f));
    return __uint_as_float(u);
}

typedef wmma::fragment<wmma::accumulator, 16, 16, 8, float> AccFrag;
typedef wmma::fragment<wmma::matrix_a, 16, 16, 8, wmma::precision::tf32, wmma::row_major> AFragR;
typedef wmma::fragment<wmma::matrix_a, 16, 16, 8, wmma::precision::tf32, wmma::col_major> AFragC;
typedef wmma::fragment<wmma::matrix_b, 16, 16, 8, wmma::precision::tf32, wmma::col_major> BFragC;
typedef wmma::fragment<wmma::matrix_b, 16, 16, 8, wmma::precision::tf32, wmma::row_major> BFragR;

// ===================== Kernel 1: SYRK (single tf32) =========================
// grid (KSPLIT, BATCH), 256 threads, double-buffered 128x32 chunk.
__global__ __launch_bounds__(256, 2)
void syrk_tc(const float* __restrict__ x) {
    __shared__ __align__(16) float Xs[2][128 * XLD];
    const int ks = blockIdx.x, b = blockIdx.y;
    const int t = threadIdx.x, w = t >> 5;
    const float* xb = x + (size_t)b * C * HW + (size_t)ks * KPART;

    const int ts = c_WS[w], te = c_WS[w + 1];
    AccFrag acc[5];
#pragma unroll
    for (int n = 0; n < 5; n++) wmma::fill_fragment(acc[n], 0.0f);

    const int r0 = t >> 3, seg = t & 7;   // r0: 0..31, seg: 0..7
    float4 R[4];
    float rs[4] = {0.f, 0.f, 0.f, 0.f};
#pragma unroll
    for (int q = 0; q < 4; q++)
        R[q] = *(const float4*)(xb + (size_t)(r0 + q * 32) * HW + seg * 4);

    for (int c = 0; c < NCHUNK; c++) {
        float* buf = Xs[c & 1];
#pragma unroll
        for (int q = 0; q < 4; q++) {
            const float4 v = R[q];
            rs[q] += v.x + v.y + v.z + v.w;
            float* p = buf + (r0 + q * 32) * XLD + seg * 4;
            p[0] = rtf32(v.x); p[1] = rtf32(v.y);
            p[2] = rtf32(v.z); p[3] = rtf32(v.w);
        }
        if (c + 1 < NCHUNK) {
            const float* xc = xb + (c + 1) * 32 + seg * 4;
#pragma unroll
            for (int q = 0; q < 4; q++)
                R[q] = *(const float4*)(xc + (size_t)(r0 + q * 32) * HW);
        }
        __syncthreads();
#pragma unroll
        for (int kk = 0; kk < 4; kk++) {
            AFragR a; BFragC bf;
            int lastI = -1, n = 0;
            for (int idx = ts; idx < te; idx++, n++) {
                const int ti = c_TI[idx], tj = c_TJ[idx];
                if (ti != lastI) {
                    wmma::load_matrix_sync(a, buf + ti * 16 * XLD + kk * 8, XLD);
                    lastI = ti;
                }
                wmma::load_matrix_sync(bf, buf + tj * 16 * XLD + kk * 8, XLD);
                wmma::mma_sync(acc[n], a, bf, acc[n]);
            }
        }
    }

    float* Gp = &g_G[ks][b][0][0];
    {
        int n = 0;
        for (int idx = ts; idx < te; idx++, n++) {
            const int ti = c_TI[idx], tj = c_TJ[idx];
            wmma::store_matrix_sync(Gp + ti * 16 * C + tj * 16, acc[n], C, wmma::mem_row_major);
            if (tj > ti)
                wmma::store_matrix_sync(Gp + tj * 16 * C + ti * 16, acc[n], C, wmma::mem_col_major);
        }
    }
#pragma unroll
    for (int q = 0; q < 4; q++) {
        rs[q] += __shfl_xor_sync(0xffffffffu, rs[q], 1);
        rs[q] += __shfl_xor_sync(0xffffffffu, rs[q], 2);
        rs[q] += __shfl_xor_sync(0xffffffffu, rs[q], 4);
    }
    if (seg == 0) {
#pragma unroll
        for (int q = 0; q < 4; q++) g_s[ks][b][r0 + q * 32] = rs[q];
    }
}

// ===================== Kernel 2: fused Newton-Schulz ========================
// grid (BATCH), 256 threads. Masters Y/Z/T fp32 in smem; per-panel hi/lo
// slabs staged k-major; split-tf32 (hh+hl+lh) MMAs = fp32-accurate.
#define NS_FLOATS (3 * 128 * MLD + 6 * 8 * SLD + 128 + 8)

__global__ __launch_bounds__(256, 1)
void ns_tc(float* __restrict__ out) {
    extern __shared__ __align__(16) float sm[];
    float* Y  = sm;
    float* Z  = Y + 128 * MLD;
    float* T  = Z + 128 * MLD;
    float* SH = T + 128 * MLD;          // 3 hi slabs [3][8][SLD]
    float* SL = SH + 3 * 8 * SLD;       // 3 lo slabs
    float* mu = SL + 3 * 8 * SLD;
    float* red = mu + 128;

    const int b = blockIdx.x;
    const int t = threadIdx.x, w = t >> 5, lane = t & 31;
    const int ts = c_WS[w], te = c_WS[w + 1];

    // ---- prologue: mean, trace, Y0 = sigma/tr, Z0 = I ----
    const float invn = 1.0f / (float)HW;
    if (t < 128) {
        float s = 0.f;
#pragma unroll
        for (int p = 0; p < KSPLIT; p++) s += g_s[p][b][t];
        mu[t] = s * invn;
    }
    __syncthreads();
    float d = 0.f;
    if (t < 128) {
        float g = 0.f;
#pragma unroll
        for (int p = 0; p < KSPLIT; p++) g += g_G[p][b][t][t];
        const float m = mu[t];
        d = g * invn - m * m;
    }
#pragma unroll
    for (int o = 16; o; o >>= 1) d += __shfl_down_sync(0xffffffffu, d, o);
    if (lane == 0) red[w] = d;
    __syncthreads();
    float tr = 0.f;
#pragma unroll
    for (int p = 0; p < 8; p++) tr += red[p];
    const float invtr = 1.0f / tr;

    for (int e = t; e < C * C; e += 256) {
        const int i = e >> 7, j = e & 127;
        float g = 0.f;
#pragma unroll
        for (int p = 0; p < KSPLIT; p++) g += g_G[p][b][i][j];
        Y[i * MLD + j] = (g * invn - mu[i] * mu[j]) * invtr;
        Z[i * MLD + j] = (i == j) ? 1.0f : 0.0f;
    }

    // slab(s)[kk][i] = M[i][k0+kk]  (k-major): A reads col_major, B row_major
#define STAGE(s, M, k0) do { \
        for (int idx = t; idx < 1024; idx += 256) { \
            const int kk = idx >> 7, i = idx & 127; \
            const float v = (M)[i * MLD + (k0) + kk]; \
            const float h = rtf32(v); \
            SH[(s) * 8 * SLD + kk * SLD + i] = h; \
            SL[(s) * 8 * SLD + kk * SLD + i] = v - h; \
        } } while (0)

    for (int it = 0; it < NUM_ITER; it++) {
        const bool lastit = (it == NUM_ITER - 1);

        // ---- phase 1: D0 = Z @ Y -> T ----
        {
            AccFrag a1[5];
#pragma unroll
            for (int n = 0; n < 5; n++) wmma::fill_fragment(a1[n], 0.0f);
            for (int k0 = 0; k0 < C; k0 += 8) {
                __syncthreads();
                STAGE(0, Z, k0);
                STAGE(1, Y, k0);
                __syncthreads();
                AFragC ah, al; BFragR bh, bl;
                int lastI = -1, n = 0;
                for (int idx = ts; idx < te; idx++, n++) {
                    const int ti = c_TI[idx], tj = c_TJ[idx];
                    if (ti != lastI) {
                        wmma::load_matrix_sync(ah, SH + 0 * 8 * SLD + ti * 16, SLD);
                        wmma::load_matrix_sync(al, SL + 0 * 8 * SLD + ti * 16, SLD);
                        lastI = ti;
                    }
                    wmma::load_matrix_sync(bh, SH + 1 * 8 * SLD + tj * 16, SLD);
                    wmma::load_matrix_sync(bl, SL + 1 * 8 * SLD + tj * 16, SLD);
                    wmma::mma_sync(a1[n], ah, bh, a1[n]);
                    wmma::mma_sync(a1[n], ah, bl, a1[n]);
                    wmma::mma_sync(a1[n], al, bh, a1[n]);
                }
            }
            // stores hit T only; slabs hold copies -> no pre-sync needed
            int n = 0;
            for (int idx = ts; idx < te; idx++, n++) {
                const int ti = c_TI[idx], tj = c_TJ[idx];
                wmma::store_matrix_sync(T + ti * 16 * MLD + tj * 16, a1[n], MLD, wmma::mem_row_major);
                if (tj > ti)
                    wmma::store_matrix_sync(T + tj * 16 * MLD + ti * 16, a1[n], MLD, wmma::mem_col_major);
            }
        }
        __syncthreads();
        // T = 1.5 I - 0.5 D0
        for (int e = t; e < C * C; e += 256) {
            const int i = e >> 7, j = e & 127;
            T[i * MLD + j] = fmaf(-0.5f, T[i * MLD + j], (i == j) ? 1.5f : 0.0f);
        }

        // ---- phase 2: Ynext = Y@T (and Znext = T@Z unless last iter) ----
        {
            AccFrag a2[5], a3[5];
#pragma unroll
            for (int n = 0; n < 5; n++) { wmma::fill_fragment(a2[n], 0.0f); wmma::fill_fragment(a3[n], 0.0f); }
            for (int k0 = 0; k0 < C; k0 += 8) {
                __syncthreads();
                STAGE(0, Y, k0);
                STAGE(1, T, k0);
                if (!lastit) STAGE(2, Z, k0);
                __syncthreads();
                AFragC ayh, ayl, ath, atl; BFragR bh, bl;
                int lastI = -1, n = 0;
                for (int idx = ts; idx < te; idx++, n++) {
                    const int ti = c_TI[idx], tj = c_TJ[idx];
                    if (ti != lastI) {
                        wmma::load_matrix_sync(ayh, SH + 0 * 8 * SLD + ti * 16, SLD);
                        wmma::load_matrix_sync(ayl, SL + 0 * 8 * SLD + ti * 16, SLD);
                        if (!lastit) {
                            wmma::load_matrix_sync(ath, SH + 1 * 8 * SLD + ti * 16, SLD);
                            wmma::load_matrix_sync(atl, SL + 1 * 8 * SLD + ti * 16, SLD);
                        }
                        lastI = ti;
                    }
                    // mm2: Y @ T
                    wmma::load_matrix_sync(bh, SH + 1 * 8 * SLD + tj * 16, SLD);
                    wmma::load_matrix_sync(bl, SL + 1 * 8 * SLD + tj * 16, SLD);
                    wmma::mma_sync(a2[n], ayh, bh, a2[n]);
                    wmma::mma_sync(a2[n], ayh, bl, a2[n]);
                    wmma::mma_sync(a2[n], ayl, bh, a2[n]);
                    if (!lastit) {
                        // mm3: T @ Z
                        wmma::load_matrix_sync(bh, SH + 2 * 8 * SLD + tj * 16, SLD);
                        wmma::load_matrix_sync(bl, SL + 2 * 8 * SLD + tj * 16, SLD);
                        wmma::mma_sync(a3[n], ath, bh, a3[n]);
                        wmma::mma_sync(a3[n], ath, bl, a3[n]);
                        wmma::mma_sync(a3[n], atl, bh, a3[n]);
                    }
                }
            }
            // stores target Y/Z masters; all panel reads go through slabs -> safe
            int n = 0;
            for (int idx = ts; idx < te; idx++, n++) {
                const int ti = c_TI[idx], tj = c_TJ[idx];
                wmma::store_matrix_sync(Y + ti * 16 * MLD + tj * 16, a2[n], MLD, wmma::mem_row_major);
                if (tj > ti)
                    wmma::store_matrix_sync(Y + tj * 16 * MLD + ti * 16, a2[n], MLD, wmma::mem_col_major);
                if (!lastit) {
                    wmma::store_matrix_sync(Z + ti * 16 * MLD + tj * 16, a3[n], MLD, wmma::mem_row_major);
                    if (tj > ti)
                        wmma::store_matrix_sync(Z + tj * 16 * MLD + ti * 16, a3[n], MLD, wmma::mem_col_major);
                }
            }
        }
        __syncthreads();
    }

    // ---- output: triu(Y * sqrt(tr)) ----
    const float s = sqrtf(tr);
    if (t < 128) {
        const int i = t;
        float* o = out + (size_t)b * TRIU + i * (257 - i) / 2;
        const float* yr = Y + i * MLD;
        for (int j = i; j < C; j++) o[j - i] = yr[j] * s;
    }
#undef STAGE
}

// =================== launch ==================================================
extern "C" void kernel_launch(void* const* d_in, const int* in_sizes, int n_in,
                              void* d_out, int out_size) {
    const float* x = (const float*)d_in[0];
    float* out = (float*)d_out;
    cudaFuncSetAttribute(ns_tc, cudaFuncAttributeMaxDynamicSharedMemorySize,
                         NS_FLOATS * (int)sizeof(float));
    dim3 g1(KSPLIT, BATCH);
    syrk_tc<<<g1, 256>>>(x);
    ns_tc<<<BATCH, 256, NS_FLOATS * sizeof(float)>>>(out);
}

// round 6
// speedup vs baseline: 2.9368x; 2.9368x over previous
#include <cuda_runtime.h>
#include <mma.h>
#include <cstdint>
#include <math.h>
using namespace nvcuda;

#define BATCH 64
#define C 128
#define HW 3136
#define KSPLIT 7
#define KPART 448        // HW / KSPLIT
#define NCHUNK 14        // KPART / 32
#define NUM_ITER 5
#define TRIU 8256
#define XLD 36           // SYRK chunk smem ld
#define MLD 132          // NS master ld

__device__ float g_G[KSPLIT][BATCH][C][C];
__device__ float g_s[KSPLIT][BATCH][C];

// 36 upper-tri 16x16 tiles -> 8 warps x 5 slots (4 pads, valid=0).
// Slots within a warp sorted by ti for A-fragment reuse.
__constant__ int8_t c_TI[8][5] = {
    {0,0,0,0,0}, {0,0,0,1,1}, {1,1,1,1,1}, {2,2,2,2,2},
    {2,3,3,3,3}, {3,4,4,4,4}, {5,5,5,6,6}, {7,0,0,0,0}};
__constant__ int8_t c_TJ[8][5] = {
    {0,1,2,3,4}, {5,6,7,1,2}, {3,4,5,6,7}, {2,3,4,5,6},
    {7,3,4,5,6}, {7,4,5,6,7}, {5,6,7,6,7}, {7,0,0,0,0}};
__constant__ int8_t c_VD[8][5] = {
    {1,1,1,1,1}, {1,1,1,1,1}, {1,1,1,1,1}, {1,1,1,1,1},
    {1,1,1,1,1}, {1,1,1,1,1}, {1,1,1,1,1}, {1,0,0,0,0}};

__device__ __forceinline__ float rtf32(float f) {
    uint32_t u; asm("cvt.rna.tf32.f32 %0, %1;" : "=r"(u) : "f"(f));
    return __uint_as_float(u);
}

typedef wmma::fragment<wmma::accumulator, 16, 16, 8, float> AccFrag;
typedef wmma::fragment<wmma::matrix_a, 16, 16, 8, wmma::precision::tf32, wmma::row_major> AFragR;
typedef wmma::fragment<wmma::matrix_b, 16, 16, 8, wmma::precision::tf32, wmma::col_major> BFragC;

// ===================== Kernel 1: SYRK via wmma tf32 =========================
// grid (KSPLIT, BATCH), 256 threads, double-buffered 128x32 chunk.
__global__ __launch_bounds__(256, 2)
void syrk_tc(const float* __restrict__ x) {
    __shared__ __align__(16) float Xs[2][128 * XLD];
    const int ks = blockIdx.x, b = blockIdx.y;
    const int t = threadIdx.x, w = t >> 5;
    const float* xb = x + (size_t)b * C * HW + (size_t)ks * KPART;

    int ti[5], tj[5], vd[5];
#pragma unroll
    for (int s = 0; s < 5; s++) { ti[s] = c_TI[w][s]; tj[s] = c_TJ[w][s]; vd[s] = c_VD[w][s]; }

    AccFrag acc[5];
#pragma unroll
    for (int s = 0; s < 5; s++) wmma::fill_fragment(acc[s], 0.0f);

    const int r0 = t >> 3, seg = t & 7;
    float4 R[4];
    float rs[4] = {0.f, 0.f, 0.f, 0.f};
#pragma unroll
    for (int q = 0; q < 4; q++)
        R[q] = *(const float4*)(xb + (size_t)(r0 + q * 32) * HW + seg * 4);

    for (int c = 0; c < NCHUNK; c++) {
        float* buf = Xs[c & 1];
#pragma unroll
        for (int q = 0; q < 4; q++) {
            const float4 v = R[q];
            rs[q] += v.x + v.y + v.z + v.w;
            float* p = buf + (r0 + q * 32) * XLD + seg * 4;
            p[0] = rtf32(v.x); p[1] = rtf32(v.y);
            p[2] = rtf32(v.z); p[3] = rtf32(v.w);
        }
        if (c + 1 < NCHUNK) {
            const float* xc = xb + (c + 1) * 32 + seg * 4;
#pragma unroll
            for (int q = 0; q < 4; q++)
                R[q] = *(const float4*)(xc + (size_t)(r0 + q * 32) * HW);
        }
        __syncthreads();
#pragma unroll
        for (int kk = 0; kk < 4; kk++) {
            AFragR a; BFragC bf;
#pragma unroll
            for (int s = 0; s < 5; s++) {
                if (s == 0 || ti[s] != ti[s - 1])
                    wmma::load_matrix_sync(a, buf + ti[s] * 16 * XLD + kk * 8, XLD);
                wmma::load_matrix_sync(bf, buf + tj[s] * 16 * XLD + kk * 8, XLD);
                wmma::mma_sync(acc[s], a, bf, acc[s]);
            }
        }
    }

    float* Gp = &g_G[ks][b][0][0];
#pragma unroll
    for (int s = 0; s < 5; s++) {
        if (vd[s]) {
            wmma::store_matrix_sync(Gp + ti[s] * 16 * C + tj[s] * 16, acc[s], C, wmma::mem_row_major);
            if (tj[s] > ti[s])
                wmma::store_matrix_sync(Gp + tj[s] * 16 * C + ti[s] * 16, acc[s], C, wmma::mem_col_major);
        }
    }
#pragma unroll
    for (int q = 0; q < 4; q++) {
        rs[q] += __shfl_xor_sync(0xffffffffu, rs[q], 1);
        rs[q] += __shfl_xor_sync(0xffffffffu, rs[q], 2);
        rs[q] += __shfl_xor_sync(0xffffffffu, rs[q], 4);
    }
    if (seg == 0) {
#pragma unroll
        for (int q = 0; q < 4; q++) g_s[ks][b][r0 + q * 32] = rs[q];
    }
}

// ===================== Kernel 2: fused Newton-Schulz ========================
// grid (BATCH), 256 threads, ~203KB smem. Masters Y/Z/T fp32 (tf32-rounded),
// symmetric -> B operand is a col_major load from the same row-major buffer.
#define NS_FLOATS (3 * 128 * MLD + 128 + 8)

__global__ __launch_bounds__(256, 1)
void ns_tc(float* __restrict__ out) {
    extern __shared__ __align__(16) float sm[];
    float* Y  = sm;
    float* Z  = Y + 128 * MLD;
    float* T  = Z + 128 * MLD;
    float* mu = T + 128 * MLD;
    float* red = mu + 128;

    const int b = blockIdx.x;
    const int t = threadIdx.x, w = t >> 5, lane = t & 31;

    int ti[5], tj[5], vd[5];
#pragma unroll
    for (int s = 0; s < 5; s++) { ti[s] = c_TI[w][s]; tj[s] = c_TJ[w][s]; vd[s] = c_VD[w][s]; }

    // ---- prologue: mean, trace, Y0 = rna(sigma/tr), Z0 = I ----
    const float invn = 1.0f / (float)HW;
    const float* Gp[KSPLIT];
#pragma unroll
    for (int p = 0; p < KSPLIT; p++) Gp[p] = &g_G[p][b][0][0];

    if (t < 128) {
        float s = 0.f;
#pragma unroll
        for (int p = 0; p < KSPLIT; p++) s += g_s[p][b][t];
        mu[t] = s * invn;
    }
    __syncthreads();
    float dsum = 0.f;
    if (t < 128) {
        float g = 0.f;
#pragma unroll
        for (int p = 0; p < KSPLIT; p++) g += Gp[p][t * C + t];
        const float m = mu[t];
        dsum = g * invn - m * m;
    }
#pragma unroll
    for (int o = 16; o; o >>= 1) dsum += __shfl_down_sync(0xffffffffu, dsum, o);
    if (lane == 0) red[w] = dsum;
    __syncthreads();
    float tr = 0.f;
#pragma unroll
    for (int p = 0; p < 8; p++) tr += red[p];
    const float invtr = 1.0f / tr;

    for (int e4 = t; e4 < 4096; e4 += 256) {
        const int i = e4 >> 5;
        const int j = (e4 & 31) * 4;
        float4 g = *(const float4*)(Gp[0] + i * C + j);
#pragma unroll
        for (int p = 1; p < KSPLIT; p++) {
            const float4 gp = *(const float4*)(Gp[p] + i * C + j);
            g.x += gp.x; g.y += gp.y; g.z += gp.z; g.w += gp.w;
        }
        const float mi = mu[i];
        float* yp = Y + i * MLD + j;
        float* zp = Z + i * MLD + j;
        yp[0] = rtf32((g.x * invn - mi * mu[j + 0]) * invtr);
        yp[1] = rtf32((g.y * invn - mi * mu[j + 1]) * invtr);
        yp[2] = rtf32((g.z * invn - mi * mu[j + 2]) * invtr);
        yp[3] = rtf32((g.w * invn - mi * mu[j + 3]) * invtr);
        zp[0] = (i == j)     ? 1.0f : 0.0f;
        zp[1] = (i == j + 1) ? 1.0f : 0.0f;
        zp[2] = (i == j + 2) ? 1.0f : 0.0f;
        zp[3] = (i == j + 3) ? 1.0f : 0.0f;
    }
    __syncthreads();

    for (int it = 0; it < NUM_ITER; it++) {
        const bool lastit = (it == NUM_ITER - 1);

        // ---- phase 1: T = Z @ Y (raw store; transform applies rna) ----
        {
            AccFrag a1[5];
#pragma unroll
            for (int s = 0; s < 5; s++) wmma::fill_fragment(a1[s], 0.0f);
            for (int k0 = 0; k0 < C; k0 += 8) {
                AFragR az; BFragC by;
#pragma unroll
                for (int s = 0; s < 5; s++) {
                    if (s == 0 || ti[s] != ti[s - 1])
                        wmma::load_matrix_sync(az, Z + ti[s] * 16 * MLD + k0, MLD);
                    wmma::load_matrix_sync(by, Y + tj[s] * 16 * MLD + k0, MLD);
                    wmma::mma_sync(a1[s], az, by, a1[s]);
                }
            }
            // T untouched by phase-1 reads -> store without pre-sync
#pragma unroll
            for (int s = 0; s < 5; s++) {
                if (vd[s]) {
                    wmma::store_matrix_sync(T + ti[s] * 16 * MLD + tj[s] * 16, a1[s], MLD, wmma::mem_row_major);
                    if (tj[s] > ti[s])
                        wmma::store_matrix_sync(T + tj[s] * 16 * MLD + ti[s] * 16, a1[s], MLD, wmma::mem_col_major);
                }
            }
        }
        __syncthreads();
        // T = rna(1.5 I - 0.5 T)
        for (int e = t; e < C * C; e += 256) {
            const int i = e >> 7, j = e & 127;
            T[i * MLD + j] = rtf32(fmaf(-0.5f, T[i * MLD + j], (i == j) ? 1.5f : 0.0f));
        }
        __syncthreads();

        // ---- phase 2: Ynew = Y@T (+ Znew = T@Z unless last) ----
        {
            AccFrag a2[5], a3[5];
#pragma unroll
            for (int s = 0; s < 5; s++) { wmma::fill_fragment(a2[s], 0.0f); wmma::fill_fragment(a3[s], 0.0f); }
            for (int k0 = 0; k0 < C; k0 += 8) {
                AFragR ay, at; BFragC bt, bz;
#pragma unroll
                for (int s = 0; s < 5; s++) {
                    if (s == 0 || ti[s] != ti[s - 1]) {
                        wmma::load_matrix_sync(ay, Y + ti[s] * 16 * MLD + k0, MLD);
                        if (!lastit)
                            wmma::load_matrix_sync(at, T + ti[s] * 16 * MLD + k0, MLD);
                    }
                    wmma::load_matrix_sync(bt, T + tj[s] * 16 * MLD + k0, MLD);
                    wmma::mma_sync(a2[s], ay, bt, a2[s]);
                    if (!lastit) {
                        wmma::load_matrix_sync(bz, Z + tj[s] * 16 * MLD + k0, MLD);
                        wmma::mma_sync(a3[s], at, bz, a3[s]);
                    }
                }
            }
            __syncthreads();   // all reads of Y/Z done before overwrite
            if (!lastit) {     // fold rna into the fragments
#pragma unroll
                for (int s = 0; s < 5; s++)
#pragma unroll
                    for (int e = 0; e < a2[s].num_elements; e++) {
                        a2[s].x[e] = rtf32(a2[s].x[e]);
                        a3[s].x[e] = rtf32(a3[s].x[e]);
                    }
            }
#pragma unroll
            for (int s = 0; s < 5; s++) {
                if (vd[s]) {
                    wmma::store_matrix_sync(Y + ti[s] * 16 * MLD + tj[s] * 16, a2[s], MLD, wmma::mem_row_major);
                    if (tj[s] > ti[s])
                        wmma::store_matrix_sync(Y + tj[s] * 16 * MLD + ti[s] * 16, a2[s], MLD, wmma::mem_col_major);
                    if (!lastit) {
                        wmma::store_matrix_sync(Z + ti[s] * 16 * MLD + tj[s] * 16, a3[s], MLD, wmma::mem_row_major);
                        if (tj[s] > ti[s])
                            wmma::store_matrix_sync(Z + tj[s] * 16 * MLD + ti[s] * 16, a3[s], MLD, wmma::mem_col_major);
                    }
                }
            }
        }
        __syncthreads();
    }

    // ---- output: triu(Y * sqrt(tr)) ----
    const float s = sqrtf(tr);
    if (t < 128) {
        const int i = t;
        float* o = out + (size_t)b * TRIU + i * (257 - i) / 2;
        const float* yr = Y + i * MLD;
        for (int j = i; j < C; j++) o[j - i] = yr[j] * s;
    }
}

// =================== launch ==================================================
extern "C" void kernel_launch(void* const* d_in, const int* in_sizes, int n_in,
                              void* d_out, int out_size) {
    const float* x = (const float*)d_in[0];
    float* out = (float*)d_out;
    cudaFuncSetAttribute(ns_tc, cudaFuncAttributeMaxDynamicSharedMemorySize,
                         NS_FLOATS * (int)sizeof(float));
    dim3 g1(KSPLIT, BATCH);
    syrk_tc<<<g1, 256>>>(x);
    ns_tc<<<BATCH, 256, NS_FLOATS * sizeof(float)>>>(out);
}

// round 7
// speedup vs baseline: 3.1049x; 1.0572x over previous
#include <cuda_runtime.h>
#include <mma.h>
#include <cstdint>
#include <math.h>
using namespace nvcuda;

#define BATCH 64
#define C 128
#define HW 3136
#define KSPLIT 7
#define KPART 448        // HW / KSPLIT
#define NCHUNK 14        // KPART / 32
#define NUM_ITER 5
#define TRIU 8256
#define XTLD 132         // SYRK transposed-chunk ld
#define MLD 132          // NS master ld

__device__ float g_G[KSPLIT][BATCH][C][C];
__device__ float g_s[KSPLIT][BATCH][C];

// 36 upper-tri 16x16 tiles over 8 warps: counts (5,5,5,5,4,4,4,4).
// Pad slot (s=4, w>=4) duplicates previous ti so no extra A load; guarded out.
__constant__ int8_t c_TI[8][5] = {
    {0,0,0,0,0}, {0,0,0,1,1}, {1,1,1,1,1}, {2,2,2,2,2},
    {2,3,3,3,3}, {3,3,4,4,4}, {4,4,5,5,5}, {5,6,6,7,7}};
__constant__ int8_t c_TJ[8][5] = {
    {0,1,2,3,4}, {5,6,7,1,2}, {3,4,5,6,7}, {2,3,4,5,6},
    {7,3,4,5,5}, {6,7,4,5,5}, {6,7,5,6,6}, {7,6,7,7,7}};

__device__ __forceinline__ float rtf32(float f) {
    uint32_t u; asm("cvt.rna.tf32.f32 %0, %1;" : "=r"(u) : "f"(f));
    return __uint_as_float(u);
}

typedef wmma::fragment<wmma::accumulator, 16, 16, 8, float> AccFrag;
typedef wmma::fragment<wmma::matrix_a, 16, 16, 8, wmma::precision::tf32, wmma::row_major> AFragR;
typedef wmma::fragment<wmma::matrix_a, 16, 16, 8, wmma::precision::tf32, wmma::col_major> AFragC;
typedef wmma::fragment<wmma::matrix_b, 16, 16, 8, wmma::precision::tf32, wmma::row_major> BFragR;

// ===================== Kernel 1: SYRK via wmma tf32 =========================
// grid (KSPLIT, BATCH), 256 threads. Only the TRANSPOSED chunk Xt[32][128]
// is stored: A = col_major frag, B = row_major frag -> contiguous frag rows.
__global__ __launch_bounds__(256, 2)
void syrk_tc(const float* __restrict__ x) {
    __shared__ __align__(16) float Xt[2][32 * XTLD];
    const int ks = blockIdx.x, b = blockIdx.y;
    const int t = threadIdx.x, w = t >> 5;
    const float* xb = x + (size_t)b * C * HW + (size_t)ks * KPART;

    int ti[5], tj[5];
#pragma unroll
    for (int s = 0; s < 5; s++) { ti[s] = c_TI[w][s]; tj[s] = c_TJ[w][s]; }

    AccFrag acc[5];
#pragma unroll
    for (int s = 0; s < 5; s++) wmma::fill_fragment(acc[s], 0.0f);

    const int r0 = t >> 3, seg = t & 7;   // r0 0..31, seg 0..7
    float4 R[4];
    float rs[4] = {0.f, 0.f, 0.f, 0.f};
#pragma unroll
    for (int q = 0; q < 4; q++)
        R[q] = *(const float4*)(xb + (size_t)(r0 + q * 32) * HW + seg * 4);

    for (int c = 0; c < NCHUNK; c++) {
        float* buf = Xt[c & 1];
#pragma unroll
        for (int q = 0; q < 4; q++) {
            const float4 v = R[q];
            rs[q] += v.x + v.y + v.z + v.w;
            const int col = r0 + q * 32;
            buf[(seg * 4 + 0) * XTLD + col] = rtf32(v.x);
            buf[(seg * 4 + 1) * XTLD + col] = rtf32(v.y);
            buf[(seg * 4 + 2) * XTLD + col] = rtf32(v.z);
            buf[(seg * 4 + 3) * XTLD + col] = rtf32(v.w);
        }
        if (c + 1 < NCHUNK) {
            const float* xc = xb + (c + 1) * 32 + seg * 4;
#pragma unroll
            for (int q = 0; q < 4; q++)
                R[q] = *(const float4*)(xc + (size_t)(r0 + q * 32) * HW);
        }
        __syncthreads();
#pragma unroll
        for (int kk0 = 0; kk0 < 32; kk0 += 8) {
            const float* kbase = buf + kk0 * XTLD;
            AFragC a; BFragR bf;
#pragma unroll
            for (int s = 0; s < 5; s++) {
                if (s == 0 || ti[s] != ti[s - 1])
                    wmma::load_matrix_sync(a, kbase + ti[s] * 16, XTLD);
                if (w < 4 || s < 4) {
                    wmma::load_matrix_sync(bf, kbase + tj[s] * 16, XTLD);
                    wmma::mma_sync(acc[s], a, bf, acc[s]);
                }
            }
        }
    }

    float* Gp = &g_G[ks][b][0][0];
#pragma unroll
    for (int s = 0; s < 5; s++) {
        if (w < 4 || s < 4) {
            wmma::store_matrix_sync(Gp + ti[s] * 16 * C + tj[s] * 16, acc[s], C, wmma::mem_row_major);
            if (tj[s] > ti[s])
                wmma::store_matrix_sync(Gp + tj[s] * 16 * C + ti[s] * 16, acc[s], C, wmma::mem_col_major);
        }
    }
#pragma unroll
    for (int q = 0; q < 4; q++) {
        rs[q] += __shfl_xor_sync(0xffffffffu, rs[q], 1);
        rs[q] += __shfl_xor_sync(0xffffffffu, rs[q], 2);
        rs[q] += __shfl_xor_sync(0xffffffffu, rs[q], 4);
    }
    if (seg == 0) {
#pragma unroll
        for (int q = 0; q < 4; q++) g_s[ks][b][r0 + q * 32] = rs[q];
    }
}

// ===================== Kernel 2: fused Newton-Schulz ========================
// grid (BATCH), 256 threads, ~203KB smem. B operands are plain row_major
// frag loads (natural layout) -> contiguous, conflict-light.
#define NS_FLOATS (3 * 128 * MLD + 128 + 8)

__global__ __launch_bounds__(256, 1)
void ns_tc(float* __restrict__ out) {
    extern __shared__ __align__(16) float sm[];
    float* Y  = sm;
    float* Z  = Y + 128 * MLD;
    float* T  = Z + 128 * MLD;
    float* mu = T + 128 * MLD;
    float* red = mu + 128;

    const int b = blockIdx.x;
    const int t = threadIdx.x, w = t >> 5, lane = t & 31;

    int ti[5], tj[5];
#pragma unroll
    for (int s = 0; s < 5; s++) { ti[s] = c_TI[w][s]; tj[s] = c_TJ[w][s]; }

    // ---- prologue: mean, trace, Y0 = rna(sigma/tr), Z0 = I ----
    const float invn = 1.0f / (float)HW;
    const float* Gp[KSPLIT];
#pragma unroll
    for (int p = 0; p < KSPLIT; p++) Gp[p] = &g_G[p][b][0][0];

    if (t < 128) {
        float s = 0.f;
#pragma unroll
        for (int p = 0; p < KSPLIT; p++) s += g_s[p][b][t];
        mu[t] = s * invn;
    }
    __syncthreads();
    float dsum = 0.f;
    if (t < 128) {
        float g = 0.f;
#pragma unroll
        for (int p = 0; p < KSPLIT; p++) g += Gp[p][t * C + t];
        const float m = mu[t];
        dsum = g * invn - m * m;
    }
#pragma unroll
    for (int o = 16; o; o >>= 1) dsum += __shfl_down_sync(0xffffffffu, dsum, o);
    if (lane == 0) red[w] = dsum;
    __syncthreads();
    float tr = 0.f;
#pragma unroll
    for (int p = 0; p < 8; p++) tr += red[p];
    const float invtr = 1.0f / tr;

    for (int e4 = t; e4 < 4096; e4 += 256) {
        const int i = e4 >> 5;
        const int j = (e4 & 31) * 4;
        float4 g = *(const float4*)(Gp[0] + i * C + j);
#pragma unroll
        for (int p = 1; p < KSPLIT; p++) {
            const float4 gp = *(const float4*)(Gp[p] + i * C + j);
            g.x += gp.x; g.y += gp.y; g.z += gp.z; g.w += gp.w;
        }
        const float mi = mu[i];
        float* yp = Y + i * MLD + j;
        float* zp = Z + i * MLD + j;
        yp[0] = rtf32((g.x * invn - mi * mu[j + 0]) * invtr);
        yp[1] = rtf32((g.y * invn - mi * mu[j + 1]) * invtr);
        yp[2] = rtf32((g.z * invn - mi * mu[j + 2]) * invtr);
        yp[3] = rtf32((g.w * invn - mi * mu[j + 3]) * invtr);
        zp[0] = (i == j)     ? 1.0f : 0.0f;
        zp[1] = (i == j + 1) ? 1.0f : 0.0f;
        zp[2] = (i == j + 2) ? 1.0f : 0.0f;
        zp[3] = (i == j + 3) ? 1.0f : 0.0f;
    }
    __syncthreads();

    for (int it = 0; it < NUM_ITER; it++) {
        const bool lastit = (it == NUM_ITER - 1);

        // ---- phase 1: T = Z @ Y ----
        {
            AccFrag a1[5];
#pragma unroll
            for (int s = 0; s < 5; s++) wmma::fill_fragment(a1[s], 0.0f);
            for (int k0 = 0; k0 < C; k0 += 8) {
                AFragR az; BFragR by;
#pragma unroll
                for (int s = 0; s < 5; s++) {
                    if (s == 0 || ti[s] != ti[s - 1])
                        wmma::load_matrix_sync(az, Z + ti[s] * 16 * MLD + k0, MLD);
                    if (w < 4 || s < 4) {
                        wmma::load_matrix_sync(by, Y + k0 * MLD + tj[s] * 16, MLD);
                        wmma::mma_sync(a1[s], az, by, a1[s]);
                    }
                }
            }
#pragma unroll
            for (int s = 0; s < 5; s++) {
                if (w < 4 || s < 4) {
                    wmma::store_matrix_sync(T + ti[s] * 16 * MLD + tj[s] * 16, a1[s], MLD, wmma::mem_row_major);
                    if (tj[s] > ti[s])
                        wmma::store_matrix_sync(T + tj[s] * 16 * MLD + ti[s] * 16, a1[s], MLD, wmma::mem_col_major);
                }
            }
        }
        __syncthreads();
        // T = rna(1.5 I - 0.5 T)
        for (int e = t; e < C * C; e += 256) {
            const int i = e >> 7, j = e & 127;
            T[i * MLD + j] = rtf32(fmaf(-0.5f, T[i * MLD + j], (i == j) ? 1.5f : 0.0f));
        }
        __syncthreads();

        // ---- phase 2: Ynew = Y@T (+ Znew = T@Z unless last) ----
        {
            AccFrag a2[5], a3[5];
#pragma unroll
            for (int s = 0; s < 5; s++) { wmma::fill_fragment(a2[s], 0.0f); wmma::fill_fragment(a3[s], 0.0f); }
            for (int k0 = 0; k0 < C; k0 += 8) {
                AFragR ay, at; BFragR bt, bz;
#pragma unroll
                for (int s = 0; s < 5; s++) {
                    if (s == 0 || ti[s] != ti[s - 1]) {
                        wmma::load_matrix_sync(ay, Y + ti[s] * 16 * MLD + k0, MLD);
                        if (!lastit)
                            wmma::load_matrix_sync(at, T + ti[s] * 16 * MLD + k0, MLD);
                    }
                    if (w < 4 || s < 4) {
                        wmma::load_matrix_sync(bt, T + k0 * MLD + tj[s] * 16, MLD);
                        wmma::mma_sync(a2[s], ay, bt, a2[s]);
                        if (!lastit) {
                            wmma::load_matrix_sync(bz, Z + k0 * MLD + tj[s] * 16, MLD);
                            wmma::mma_sync(a3[s], at, bz, a3[s]);
                        }
                    }
                }
            }
            __syncthreads();   // all reads of Y/Z done before overwrite
            if (!lastit) {
#pragma unroll
                for (int s = 0; s < 5; s++)
#pragma unroll
                    for (int e = 0; e < a2[s].num_elements; e++) {
                        a2[s].x[e] = rtf32(a2[s].x[e]);
                        a3[s].x[e] = rtf32(a3[s].x[e]);
                    }
            }
#pragma unroll
            for (int s = 0; s < 5; s++) {
                if (w < 4 || s < 4) {
                    wmma::store_matrix_sync(Y + ti[s] * 16 * MLD + tj[s] * 16, a2[s], MLD, wmma::mem_row_major);
                    if (tj[s] > ti[s])
                        wmma::store_matrix_sync(Y + tj[s] * 16 * MLD + ti[s] * 16, a2[s], MLD, wmma::mem_col_major);
                    if (!lastit) {
                        wmma::store_matrix_sync(Z + ti[s] * 16 * MLD + tj[s] * 16, a3[s], MLD, wmma::mem_row_major);
                        if (tj[s] > ti[s])
                            wmma::store_matrix_sync(Z + tj[s] * 16 * MLD + ti[s] * 16, a3[s], MLD, wmma::mem_col_major);
                    }
                }
            }
        }
        __syncthreads();
    }

    // ---- output: triu(Y * sqrt(tr)) ----
    const float s = sqrtf(tr);
    if (t < 128) {
        const int i = t;
        float* o = out + (size_t)b * TRIU + i * (257 - i) / 2;
        const float* yr = Y + i * MLD;
        for (int j = i; j < C; j++) o[j - i] = yr[j] * s;
    }
}

// =================== launch ==================================================
extern "C" void kernel_launch(void* const* d_in, const int* in_sizes, int n_in,
                              void* d_out, int out_size) {
    const float* x = (const float*)d_in[0];
    float* out = (float*)d_out;
    cudaFuncSetAttribute(ns_tc, cudaFuncAttributeMaxDynamicSharedMemorySize,
                         NS_FLOATS * (int)sizeof(float));
    dim3 g1(KSPLIT, BATCH);
    syrk_tc<<<g1, 256>>>(x);
    ns_tc<<<BATCH, 256, NS_FLOATS * sizeof(float)>>>(out);
}

// round 8
// speedup vs baseline: 3.3861x; 1.0906x over previous
#include <cuda_runtime.h>
#include <mma.h>
#include <cstdint>
#include <math.h>
using namespace nvcuda;

#define BATCH 64
#define C 128
#define HW 3136
#define KSPLIT 7
#define KPART 448        // HW / KSPLIT
#define NCHUNK 14        // KPART / 32
#define NUM_ITER 5
#define TRIU 8256
#define XTLD 132         // SYRK transposed-chunk ld
#define MLD 132          // NS master ld
#define NSTHR 384        // NS threads (12 warps x 3 tiles = 36 exactly)

__device__ float g_G[KSPLIT][BATCH][C][C];
__device__ float g_s[KSPLIT][BATCH][C];

// SYRK: 36 tiles over 8 warps (5,5,5,5,4,4,4,4); pad slot guarded by (w<4||s<4)
__constant__ int8_t c_TI[8][5] = {
    {0,0,0,0,0}, {0,0,0,1,1}, {1,1,1,1,1}, {2,2,2,2,2},
    {2,3,3,3,3}, {3,3,4,4,4}, {4,4,5,5,5}, {5,6,6,7,7}};
__constant__ int8_t c_TJ[8][5] = {
    {0,1,2,3,4}, {5,6,7,1,2}, {3,4,5,6,7}, {2,3,4,5,6},
    {7,3,4,5,5}, {6,7,4,5,5}, {6,7,5,6,6}, {7,6,7,7,7}};

// NS: 36 tiles over 12 warps x 3 slots, zero padding, sorted by ti.
__constant__ int8_t n_TI[12][3] = {
    {0,0,0}, {0,0,0}, {0,0,1}, {1,1,1}, {1,1,1}, {2,2,2},
    {2,2,2}, {3,3,3}, {3,3,4}, {4,4,4}, {5,5,5}, {6,6,7}};
__constant__ int8_t n_TJ[12][3] = {
    {0,1,2}, {3,4,5}, {6,7,1}, {2,3,4}, {5,6,7}, {2,3,4},
    {5,6,7}, {3,4,5}, {6,7,4}, {5,6,7}, {5,6,7}, {6,7,7}};

__device__ __forceinline__ float rtf32(float f) {
    uint32_t u; asm("cvt.rna.tf32.f32 %0, %1;" : "=r"(u) : "f"(f));
    return __uint_as_float(u);
}

typedef wmma::fragment<wmma::accumulator, 16, 16, 8, float> AccFrag;
typedef wmma::fragment<wmma::matrix_a, 16, 16, 8, wmma::precision::tf32, wmma::row_major> AFragR;
typedef wmma::fragment<wmma::matrix_a, 16, 16, 8, wmma::precision::tf32, wmma::col_major> AFragC;
typedef wmma::fragment<wmma::matrix_b, 16, 16, 8, wmma::precision::tf32, wmma::row_major> BFragR;

// ===================== Kernel 1: SYRK via wmma tf32 =========================
// grid (KSPLIT, BATCH), 256 threads. Upper-tri tiles ONLY to gmem (no mirror).
__global__ __launch_bounds__(256, 2)
void syrk_tc(const float* __restrict__ x) {
    __shared__ __align__(16) float Xt[2][32 * XTLD];
    const int ks = blockIdx.x, b = blockIdx.y;
    const int t = threadIdx.x, w = t >> 5;
    const float* xb = x + (size_t)b * C * HW + (size_t)ks * KPART;

    int ti[5], tj[5];
#pragma unroll
    for (int s = 0; s < 5; s++) { ti[s] = c_TI[w][s]; tj[s] = c_TJ[w][s]; }

    AccFrag acc[5];
#pragma unroll
    for (int s = 0; s < 5; s++) wmma::fill_fragment(acc[s], 0.0f);

    const int r0 = t >> 3, seg = t & 7;
    float4 R[4];
    float rs[4] = {0.f, 0.f, 0.f, 0.f};
#pragma unroll
    for (int q = 0; q < 4; q++)
        R[q] = *(const float4*)(xb + (size_t)(r0 + q * 32) * HW + seg * 4);

    for (int c = 0; c < NCHUNK; c++) {
        float* buf = Xt[c & 1];
#pragma unroll
        for (int q = 0; q < 4; q++) {
            const float4 v = R[q];
            rs[q] += v.x + v.y + v.z + v.w;
            const int col = r0 + q * 32;
            buf[(seg * 4 + 0) * XTLD + col] = rtf32(v.x);
            buf[(seg * 4 + 1) * XTLD + col] = rtf32(v.y);
            buf[(seg * 4 + 2) * XTLD + col] = rtf32(v.z);
            buf[(seg * 4 + 3) * XTLD + col] = rtf32(v.w);
        }
        if (c + 1 < NCHUNK) {
            const float* xc = xb + (c + 1) * 32 + seg * 4;
#pragma unroll
            for (int q = 0; q < 4; q++)
                R[q] = *(const float4*)(xc + (size_t)(r0 + q * 32) * HW);
        }
        __syncthreads();
#pragma unroll
        for (int kk0 = 0; kk0 < 32; kk0 += 8) {
            const float* kbase = buf + kk0 * XTLD;
            AFragC a; BFragR bf;
#pragma unroll
            for (int s = 0; s < 5; s++) {
                if (s == 0 || ti[s] != ti[s - 1])
                    wmma::load_matrix_sync(a, kbase + ti[s] * 16, XTLD);
                if (w < 4 || s < 4) {
                    wmma::load_matrix_sync(bf, kbase + tj[s] * 16, XTLD);
                    wmma::mma_sync(acc[s], a, bf, acc[s]);
                }
            }
        }
    }

    float* Gp = &g_G[ks][b][0][0];
#pragma unroll
    for (int s = 0; s < 5; s++) {
        if (w < 4 || s < 4)
            wmma::store_matrix_sync(Gp + ti[s] * 16 * C + tj[s] * 16, acc[s], C, wmma::mem_row_major);
    }
#pragma unroll
    for (int q = 0; q < 4; q++) {
        rs[q] += __shfl_xor_sync(0xffffffffu, rs[q], 1);
        rs[q] += __shfl_xor_sync(0xffffffffu, rs[q], 2);
        rs[q] += __shfl_xor_sync(0xffffffffu, rs[q], 4);
    }
    if (seg == 0) {
#pragma unroll
        for (int q = 0; q < 4; q++) g_s[ks][b][r0 + q * 32] = rs[q];
    }
}

// ===================== Kernel 2: fused Newton-Schulz ========================
// grid (BATCH), 384 threads / 12 warps / 3 tiles each (perfect balance).
#define NS_FLOATS (3 * 128 * MLD + 128 + 16)

__global__ __launch_bounds__(NSTHR, 1)
void ns_tc(float* __restrict__ out) {
    extern __shared__ __align__(16) float sm[];
    float* Y  = sm;
    float* Z  = Y + 128 * MLD;
    float* T  = Z + 128 * MLD;
    float* mu = T + 128 * MLD;
    float* red = mu + 128;

    const int b = blockIdx.x;
    const int t = threadIdx.x, w = t >> 5, lane = t & 31;

    int ti[3], tj[3];
#pragma unroll
    for (int s = 0; s < 3; s++) { ti[s] = n_TI[w][s]; tj[s] = n_TJ[w][s]; }

    // ---- prologue: mean, trace, Y0 = rna(sigma/tr) ----
    const float invn = 1.0f / (float)HW;
    const float* Gp[KSPLIT];
#pragma unroll
    for (int p = 0; p < KSPLIT; p++) Gp[p] = &g_G[p][b][0][0];

    if (t < 128) {
        float s = 0.f;
#pragma unroll
        for (int p = 0; p < KSPLIT; p++) s += g_s[p][b][t];
        mu[t] = s * invn;
    }
    __syncthreads();
    float dsum = 0.f;
    if (t < 128) {
        float g = 0.f;
#pragma unroll
        for (int p = 0; p < KSPLIT; p++) g += Gp[p][t * C + t];
        const float m = mu[t];
        dsum = g * invn - m * m;
    }
#pragma unroll
    for (int o = 16; o; o >>= 1) dsum += __shfl_down_sync(0xffffffffu, dsum, o);
    if (t < 128 && lane == 0) red[w] = dsum;
    __syncthreads();
    const float tr = red[0] + red[1] + red[2] + red[3];
    const float invtr = 1.0f / tr;

    // Y0 from UPPER triangle of G only; mirror into smem.
    for (int pos = t; pos < TRIU; pos += NSTHR) {
        int i = (int)((257.0f - sqrtf(66049.0f - 8.0f * (float)pos)) * 0.5f);
        if (i < 0) i = 0;
        if (i > 127) i = 127;
        while (i > 0 && i * (257 - i) / 2 > pos) i--;
        while (i < 127 && (i + 1) * (257 - (i + 1)) / 2 <= pos) i++;
        const int j = i + (pos - i * (257 - i) / 2);
        float g = 0.f;
#pragma unroll
        for (int p = 0; p < KSPLIT; p++) g += Gp[p][i * C + j];
        const float y0 = rtf32((g * invn - mu[i] * mu[j]) * invtr);
        Y[i * MLD + j] = y0;
        Y[j * MLD + i] = y0;
    }
    __syncthreads();

    for (int it = 0; it < NUM_ITER; it++) {
        const bool lastit = (it == NUM_ITER - 1);
        const bool doZ = (it >= 1 && !lastit);

        if (it == 0) {
            // Z0 = I  =>  T0 = 1.5I - 0.5*Y0 elementwise; Z1 = T0
            for (int e = t; e < C * C; e += NSTHR) {
                const int i = e >> 7, j = e & 127;
                const float v = rtf32(fmaf(-0.5f, Y[i * MLD + j], (i == j) ? 1.5f : 0.0f));
                T[i * MLD + j] = v;
                Z[i * MLD + j] = v;
            }
            __syncthreads();
        } else {
            // ---- phase 1: T = rna(-0.5 * (Z @ Y)), then diag += 1.5 ----
            AccFrag a1[3];
#pragma unroll
            for (int s = 0; s < 3; s++) wmma::fill_fragment(a1[s], 0.0f);
            for (int k0 = 0; k0 < C; k0 += 8) {
                AFragR az; BFragR by;
#pragma unroll
                for (int s = 0; s < 3; s++) {
                    if (s == 0 || ti[s] != ti[s - 1])
                        wmma::load_matrix_sync(az, Z + ti[s] * 16 * MLD + k0, MLD);
                    wmma::load_matrix_sync(by, Y + k0 * MLD + tj[s] * 16, MLD);
                    wmma::mma_sync(a1[s], az, by, a1[s]);
                }
            }
#pragma unroll
            for (int s = 0; s < 3; s++) {
#pragma unroll
                for (int e = 0; e < a1[s].num_elements; e++)
                    a1[s].x[e] = rtf32(-0.5f * a1[s].x[e]);
                wmma::store_matrix_sync(T + ti[s] * 16 * MLD + tj[s] * 16, a1[s], MLD, wmma::mem_row_major);
                if (tj[s] > ti[s])
                    wmma::store_matrix_sync(T + tj[s] * 16 * MLD + ti[s] * 16, a1[s], MLD, wmma::mem_col_major);
            }
            __syncthreads();
            if (t < 128) T[t * MLD + t] = rtf32(1.5f + T[t * MLD + t]);
            __syncthreads();
        }

        // ---- phase 2: Ynew = Y@T  (+ Znew = T@Z when doZ) ----
        {
            AccFrag a2[3], a3[3];
#pragma unroll
            for (int s = 0; s < 3; s++) { wmma::fill_fragment(a2[s], 0.0f); wmma::fill_fragment(a3[s], 0.0f); }
            for (int k0 = 0; k0 < C; k0 += 8) {
                AFragR ay, at; BFragR bt, bz;
#pragma unroll
                for (int s = 0; s < 3; s++) {
                    if (s == 0 || ti[s] != ti[s - 1]) {
                        wmma::load_matrix_sync(ay, Y + ti[s] * 16 * MLD + k0, MLD);
                        if (doZ)
                            wmma::load_matrix_sync(at, T + ti[s] * 16 * MLD + k0, MLD);
                    }
                    wmma::load_matrix_sync(bt, T + k0 * MLD + tj[s] * 16, MLD);
                    wmma::mma_sync(a2[s], ay, bt, a2[s]);
                    if (doZ) {
                        wmma::load_matrix_sync(bz, Z + k0 * MLD + tj[s] * 16, MLD);
                        wmma::mma_sync(a3[s], at, bz, a3[s]);
                    }
                }
            }
            __syncthreads();   // all reads of Y/Z complete before overwrite
            if (!lastit) {
#pragma unroll
                for (int s = 0; s < 3; s++)
#pragma unroll
                    for (int e = 0; e < a2[s].num_elements; e++) {
                        a2[s].x[e] = rtf32(a2[s].x[e]);
                        a3[s].x[e] = rtf32(a3[s].x[e]);
                    }
            }
#pragma unroll
            for (int s = 0; s < 3; s++) {
                wmma::store_matrix_sync(Y + ti[s] * 16 * MLD + tj[s] * 16, a2[s], MLD, wmma::mem_row_major);
                if (tj[s] > ti[s])
                    wmma::store_matrix_sync(Y + tj[s] * 16 * MLD + ti[s] * 16, a2[s], MLD, wmma::mem_col_major);
                if (doZ) {
                    wmma::store_matrix_sync(Z + ti[s] * 16 * MLD + tj[s] * 16, a3[s], MLD, wmma::mem_row_major);
                    if (tj[s] > ti[s])
                        wmma::store_matrix_sync(Z + tj[s] * 16 * MLD + ti[s] * 16, a3[s], MLD, wmma::mem_col_major);
                }
            }
        }
        __syncthreads();
    }

    // ---- output: triu(Y * sqrt(tr)) ----
    const float s = sqrtf(tr);
    if (t < 128) {
        const int i = t;
        float* o = out + (size_t)b * TRIU + i * (257 - i) / 2;
        const float* yr = Y + i * MLD;
        for (int j = i; j < C; j++) o[j - i] = yr[j] * s;
    }
}

// =================== launch ==================================================
extern "C" void kernel_launch(void* const* d_in, const int* in_sizes, int n_in,
                              void* d_out, int out_size) {
    const float* x = (const float*)d_in[0];
    float* out = (float*)d_out;
    cudaFuncSetAttribute(ns_tc, cudaFuncAttributeMaxDynamicSharedMemorySize,
                         NS_FLOATS * (int)sizeof(float));
    dim3 g1(KSPLIT, BATCH);
    syrk_tc<<<g1, 256>>>(x);
    ns_tc<<<BATCH, NSTHR, NS_FLOATS * sizeof(float)>>>(out);
}